// round 11
// baseline (speedup 1.0000x reference)
#include <cuda_runtime.h>
#include <cuda_bf16.h>
#include <math.h>
#include <stdint.h>

// ---------------- problem constants ----------------
#define NQ    200
#define NS    25
#define SEQL  8
#define DIN   2048
#define DOUT  1152
#define NTUP  56
#define WAYS  5
#define SHOTS 5
#define NTOT  (NS + NQ)        // 225
#define XROWS (NTOT * SEQL)    // 1800
#define MROWS (NTOT * 6)       // 1350 packed rows per j in gemm_main
#define SROWS (NS * NTUP)      // 1400
#define QROWS (NQ * NTUP)      // 11200
#define KROWS (NTOT * NTUP)    // 12600

#define SCALE_QK 0.029462782549439477f   // 1/sqrt(1152)

// ---------------- scratch ----------------
__device__ __nv_bfloat16 d_XP[XROWS * DIN];                    // bf16(x + pe)
__device__ __nv_bfloat16 d_Wt[2 * 3 * DOUT * DIN];             // transposed bf16 weights [w][j][n][k]
__device__ float d_Pk[XROWS * 3 * DOUT];
__device__ float d_Pv[XROWS * 3 * DOUT];
__device__ __nv_bfloat16 d_K[KROWS * DOUT];                    // bf16 LN(K)
__device__ float d_V[KROWS * DOUT];                            // fp32 exact V
__device__ __nv_bfloat16 d_Vtt[WAYS * DOUT * 320];             // support V transposed [c][d][320], shot-padded
__device__ float d_S[(size_t)QROWS * SROWS];                   // fp32 scores
__device__ __nv_bfloat16 d_At[(size_t)QROWS * WAYS * 320];     // bf16 attn, shot-padded 5*64
__device__ float d_part[NQ * WAYS * 3];                        // stage F partials per d-split

__constant__ int TUP[NTUP][3] = {
 {0,1,2},{0,1,3},{0,1,4},{0,1,5},{0,1,6},{0,1,7},
 {0,2,3},{0,2,4},{0,2,5},{0,2,6},{0,2,7},
 {0,3,4},{0,3,5},{0,3,6},{0,3,7},
 {0,4,5},{0,4,6},{0,4,7},
 {0,5,6},{0,5,7},
 {0,6,7},
 {1,2,3},{1,2,4},{1,2,5},{1,2,6},{1,2,7},
 {1,3,4},{1,3,5},{1,3,6},{1,3,7},
 {1,4,5},{1,4,6},{1,4,7},
 {1,5,6},{1,5,7},
 {1,6,7},
 {2,3,4},{2,3,5},{2,3,6},{2,3,7},
 {2,4,5},{2,4,6},{2,4,7},
 {2,5,6},{2,5,7},
 {2,6,7},
 {3,4,5},{3,4,6},{3,4,7},
 {3,5,6},{3,5,7},
 {3,6,7},
 {4,5,6},{4,5,7},{4,6,7},
 {5,6,7}
};

// ---------------- helpers ----------------
__device__ __forceinline__ void mma16(float* c, const unsigned* a, unsigned b0, unsigned b1) {
    asm volatile(
        "mma.sync.aligned.m16n8k16.row.col.f32.bf16.bf16.f32 "
        "{%0,%1,%2,%3}, {%4,%5,%6,%7}, {%8,%9}, {%0,%1,%2,%3};"
        : "+f"(c[0]), "+f"(c[1]), "+f"(c[2]), "+f"(c[3])
        : "r"(a[0]), "r"(a[1]), "r"(a[2]), "r"(a[3]), "r"(b0), "r"(b1));
}

__device__ __forceinline__ void cpa16(unsigned dst, const void* src, bool pred) {
    int sz = pred ? 16 : 0;
    asm volatile("cp.async.cg.shared.global [%0], [%1], 16, %2;\n"
                 :: "r"(dst), "l"(src), "r"(sz));
}
#define CP_COMMIT() asm volatile("cp.async.commit_group;\n")
#define CP_WAIT(n)  asm volatile("cp.async.wait_group %0;\n" :: "n"(n))

// ---------------- stage A0: transpose + convert W -> d_Wt [w][j][n][k] bf16 ----
__global__ void conv_wt_kernel(const float* __restrict__ Wk,
                               const float* __restrict__ Wv) {
    __shared__ float t[32][33];
    int z = blockIdx.z;
    int w = z / 3, j = z - w * 3;
    const float* __restrict__ W = w ? Wv : Wk;
    int k0 = blockIdx.x * 32, n0 = blockIdx.y * 32;
    int tx = threadIdx.x, ty = threadIdx.y;
#pragma unroll
    for (int r = 0; r < 4; r++) {
        int k = k0 + ty + r * 8;
        t[ty + r * 8][tx] = W[(size_t)(j * DIN + k) * DOUT + n0 + tx];
    }
    __syncthreads();
#pragma unroll
    for (int r = 0; r < 4; r++) {
        int n = n0 + ty + r * 8;
        d_Wt[((size_t)(w * 3 + j) * DOUT + n) * DIN + k0 + tx] =
            __float2bfloat16_rn(t[tx][ty + r * 8]);
    }
}

// ---------------- stage A: x + PE -> bf16 ----------------
__global__ void pe_add_kernel(const float* __restrict__ sup,
                              const float* __restrict__ qry) {
    int row = blockIdx.x;
    int i = row >> 3, l = row & 7;
    const float* src = (i < NS)
        ? sup + ((size_t)i * SEQL + l) * DIN
        : qry + ((size_t)(i - NS) * SEQL + l) * DIN;
    __nv_bfloat16* dst = d_XP + (size_t)row * DIN;
    const float kfac = -9.210340371976184f / (float)DIN;
    for (int d = threadIdx.x; d < DIN; d += blockDim.x) {
        int k2 = d & ~1;
        float arg = (float)l * expf((float)k2 * kfac);
        float pe = ((d & 1) ? cosf(arg) : sinf(arg)) * 0.1f;
        dst[d] = __float2bfloat16_rn(src[d] + pe);
    }
}

// ---------------- stage B: P = XP @ W_blocks (bf16, packed M=1350/j) ----------
// grid (9, 11, 6); block 128 (4 warps, 2m x 2n, each 64x64)
#define G_TS (128 * 36)
#define G_SMEM (4 * G_TS * 4)

__global__ void __launch_bounds__(128) gemm_main_tc() {
    extern __shared__ unsigned sh[];
    unsigned* As = sh;
    unsigned* Bs = sh + 2 * G_TS;
    unsigned as_base = (unsigned)__cvta_generic_to_shared(As);
    unsigned bs_base = (unsigned)__cvta_generic_to_shared(Bs);

    int z = blockIdx.z;
    int w = z / 3, j = z - w * 3;
    const __nv_bfloat16* __restrict__ Bp = d_Wt + (size_t)(w * 3 + j) * DOUT * DIN;
    float* __restrict__ C = w ? d_Pv : d_Pk;

    int bm = blockIdx.y * 128, bn = blockIdx.x * 128;
    int tid = threadIdx.x, lane = tid & 31, wid = tid >> 5;
    int wm = (wid & 1) * 64, wn = (wid >> 1) * 64;
    int lg = lane >> 2, lr = lane & 3;

    float acc[4][8][4];
#pragma unroll
    for (int mi = 0; mi < 4; mi++)
#pragma unroll
        for (int ni = 0; ni < 8; ni++)
#pragma unroll
            for (int e = 0; e < 4; e++) acc[mi][ni][e] = 0.f;

    auto load_stage = [&](int s, int k0) {
#pragma unroll
        for (int i = 0; i < 8; i++) {
            int e = tid + i * 128;
            int row = e >> 3, ch = e & 7;
            int grow = bm + row;
            bool pa = grow < MROWS;
            int ii = pa ? grow / 6 : 0;
            int ll = pa ? j + (grow - ii * 6) : 0;
            const __nv_bfloat16* ga =
                d_XP + (size_t)(ii * 8 + ll) * DIN + k0 + ch * 8;
            cpa16(as_base + (s * G_TS + row * 36 + ch * 4) * 4, ga, pa);
            const __nv_bfloat16* gb =
                Bp + (size_t)(bn + row) * DIN + k0 + ch * 8;
            cpa16(bs_base + (s * G_TS + row * 36 + ch * 4) * 4, gb, true);
        }
    };

    const int KT = DIN / 64;   // 32
    load_stage(0, 0);
    CP_COMMIT();
    int buf = 0;
    for (int kt = 0; kt < KT; kt++) {
        if (kt + 1 < KT) {
            load_stage(buf ^ 1, (kt + 1) * 64);
            CP_COMMIT();
            CP_WAIT(1);
        } else {
            CP_WAIT(0);
        }
        __syncthreads();
        const unsigned* Aq = As + buf * G_TS;
        const unsigned* Bq = Bs + buf * G_TS;
#pragma unroll
        for (int ks = 0; ks < 4; ks++) {
            int kw = ks * 8;
            unsigned af[4][4];
#pragma unroll
            for (int mi = 0; mi < 4; mi++) {
                int m = wm + mi * 16 + lg;
                af[mi][0] = Aq[m * 36 + kw + lr];
                af[mi][1] = Aq[(m + 8) * 36 + kw + lr];
                af[mi][2] = Aq[m * 36 + kw + lr + 4];
                af[mi][3] = Aq[(m + 8) * 36 + kw + lr + 4];
            }
#pragma unroll
            for (int ni = 0; ni < 8; ni++) {
                int n = wn + ni * 8 + lg;
                unsigned b0 = Bq[n * 36 + kw + lr];
                unsigned b1 = Bq[n * 36 + kw + lr + 4];
#pragma unroll
                for (int mi = 0; mi < 4; mi++)
                    mma16(acc[mi][ni], af[mi], b0, b1);
            }
        }
        __syncthreads();
        buf ^= 1;
    }
#pragma unroll
    for (int mi = 0; mi < 4; mi++) {
        int r0 = bm + wm + mi * 16 + lg;
        int r1 = r0 + 8;
        int i0 = r0 / 6, l0 = j + (r0 - i0 * 6);
        int i1 = r1 / 6, l1 = j + (r1 - i1 * 6);
#pragma unroll
        for (int ni = 0; ni < 8; ni++) {
            int cb = bn + wn + ni * 8 + lr * 2;
            if (r0 < MROWS) {
                float* p = &C[((size_t)(i0 * 8 + l0) * 3 + j) * DOUT + cb];
                p[0] = acc[mi][ni][0]; p[1] = acc[mi][ni][1];
            }
            if (r1 < MROWS) {
                float* p = &C[((size_t)(i1 * 8 + l1) * 3 + j) * DOUT + cb];
                p[0] = acc[mi][ni][2]; p[1] = acc[mi][ni][3];
            }
        }
    }
}

// ---------------- stage C: tuple-sum + bias (+LN for K), float4 ----------------
__global__ void tuple_ln_kernel(const float* __restrict__ bk,
                                const float* __restrict__ bv,
                                const float* __restrict__ lnw,
                                const float* __restrict__ lnb) {
    int it = blockIdx.x;
    int i = it / NTUP, t = it - i * NTUP;
    int l0 = TUP[t][0], l1 = TUP[t][1], l2 = TUP[t][2];
    const float4* pk0 = (const float4*)&d_Pk[((size_t)(i * SEQL + l0) * 3 + 0) * DOUT];
    const float4* pk1 = (const float4*)&d_Pk[((size_t)(i * SEQL + l1) * 3 + 1) * DOUT];
    const float4* pk2 = (const float4*)&d_Pk[((size_t)(i * SEQL + l2) * 3 + 2) * DOUT];
    const float4* pv0 = (const float4*)&d_Pv[((size_t)(i * SEQL + l0) * 3 + 0) * DOUT];
    const float4* pv1 = (const float4*)&d_Pv[((size_t)(i * SEQL + l1) * 3 + 1) * DOUT];
    const float4* pv2 = (const float4*)&d_Pv[((size_t)(i * SEQL + l2) * 3 + 2) * DOUT];
    const float4* bk4 = (const float4*)bk;
    const float4* bv4 = (const float4*)bv;
    const float4* lw4 = (const float4*)lnw;
    const float4* lb4 = (const float4*)lnb;
    float4* v4 = (float4*)&d_V[(size_t)it * DOUT];
    uint2* k2o = (uint2*)&d_K[(size_t)it * DOUT];

    int tid = threadIdx.x;
    float4 kv[3];
    float s = 0.f, sq = 0.f;
#pragma unroll
    for (int e = 0; e < 3; e++) {
        int o4 = tid + e * 128;
        if (o4 < 288) {
            float4 a = pk0[o4], b = pk1[o4], c = pk2[o4], d = bk4[o4];
            float4 v;
            v.x = a.x + b.x + c.x + d.x;
            v.y = a.y + b.y + c.y + d.y;
            v.z = a.z + b.z + c.z + d.z;
            v.w = a.w + b.w + c.w + d.w;
            kv[e] = v;
            s  += v.x + v.y + v.z + v.w;
            sq += v.x * v.x + v.y * v.y + v.z * v.z + v.w * v.w;
            float4 e0 = pv0[o4], e1 = pv1[o4], e2 = pv2[o4], e3 = bv4[o4];
            float4 vv;
            vv.x = e0.x + e1.x + e2.x + e3.x;
            vv.y = e0.y + e1.y + e2.y + e3.y;
            vv.z = e0.z + e1.z + e2.z + e3.z;
            vv.w = e0.w + e1.w + e2.w + e3.w;
            v4[o4] = vv;
        }
    }
#pragma unroll
    for (int o = 16; o; o >>= 1) {
        s  += __shfl_xor_sync(0xffffffffu, s,  o);
        sq += __shfl_xor_sync(0xffffffffu, sq, o);
    }
    __shared__ float ss[4], sqq[4];
    if ((tid & 31) == 0) { ss[tid >> 5] = s; sqq[tid >> 5] = sq; }
    __syncthreads();
    s  = ss[0] + ss[1] + ss[2] + ss[3];
    sq = sqq[0] + sqq[1] + sqq[2] + sqq[3];
    float mean = s * (1.0f / DOUT);
    float var  = sq * (1.0f / DOUT) - mean * mean;
    float rstd = rsqrtf(var + 1e-5f);
#pragma unroll
    for (int e = 0; e < 3; e++) {
        int o4 = tid + e * 128;
        if (o4 < 288) {
            float4 w = lw4[o4], b = lb4[o4], v = kv[e];
            float x0 = (v.x - mean) * rstd * w.x + b.x;
            float x1 = (v.y - mean) * rstd * w.y + b.y;
            float x2 = (v.z - mean) * rstd * w.z + b.z;
            float x3 = (v.w - mean) * rstd * w.w + b.w;
            __nv_bfloat162 lo = __floats2bfloat162_rn(x0, x1);
            __nv_bfloat162 hi = __floats2bfloat162_rn(x2, x3);
            uint2 o2;
            o2.x = *(unsigned*)&lo;
            o2.y = *(unsigned*)&hi;
            k2o[o4] = o2;
        }
    }
}

// ---------------- stage C2: transpose support V -> d_Vtt [c][d][320] bf16 ------
__global__ void vtrans_kernel() {
    __shared__ float t[32][33];
    int c = blockIdx.z;
    int k0 = blockIdx.x * 32, d0 = blockIdx.y * 32;
    int tx = threadIdx.x, ty = threadIdx.y;
#pragma unroll
    for (int r = 0; r < 4; r++) {
        int kc = k0 + ty + r * 8;
        if (kc < 280)
            t[ty + r * 8][tx] = d_V[(size_t)(c * 280 + kc) * DOUT + d0 + tx];
    }
    __syncthreads();
#pragma unroll
    for (int r = 0; r < 4; r++) {
        int d = d0 + ty + r * 8;
        int kc = k0 + tx;
        if (kc < 280) {
            int sh = kc / 56, tt = kc - sh * 56;
            d_Vtt[((size_t)c * DOUT + d) * 320 + sh * 64 + tt] =
                __float2bfloat16_rn(t[tx][ty + r * 8]);
        }
    }
    if (blockIdx.x == 0) {
        for (int pp = ty * 32 + tx; pp < 32 * 40; pp += 256) {
            int dd = pp / 40, po = pp - dd * 40;
            int sh = po >> 3, t8 = po & 7;
            d_Vtt[((size_t)c * DOUT + d0 + dd) * 320 + sh * 64 + 56 + t8] =
                __float2bfloat16_rn(0.f);
        }
    }
}

// ---------------- stage D: scores (bf16, 64x64 warp tiles, BK=64, 2-stage) ----
// grid (11, 88); block 128
__global__ void __launch_bounds__(128) gemm_scores_tc() {
    extern __shared__ unsigned sh[];
    unsigned* As = sh;
    unsigned* Bs = sh + 2 * G_TS;
    unsigned as_base = (unsigned)__cvta_generic_to_shared(As);
    unsigned bs_base = (unsigned)__cvta_generic_to_shared(Bs);

    const __nv_bfloat16* __restrict__ A  = d_K + (size_t)SROWS * DOUT;
    const __nv_bfloat16* __restrict__ Bm = d_K;

    int bm = blockIdx.y * 128, bn = blockIdx.x * 128;
    int tid = threadIdx.x, lane = tid & 31, wid = tid >> 5;
    int wm = (wid & 1) * 64, wn = (wid >> 1) * 64;
    int lg = lane >> 2, lr = lane & 3;

    float acc[4][8][4];
#pragma unroll
    for (int mi = 0; mi < 4; mi++)
#pragma unroll
        for (int ni = 0; ni < 8; ni++)
#pragma unroll
            for (int e = 0; e < 4; e++) acc[mi][ni][e] = 0.f;

    auto load_stage = [&](int s, int k0) {
#pragma unroll
        for (int i = 0; i < 8; i++) {
            int e = tid + i * 128;
            int row = e >> 3, ch = e & 7;
            bool pa = (bm + row) < QROWS;
            const __nv_bfloat16* ga =
                A + (size_t)(pa ? bm + row : 0) * DOUT + k0 + ch * 8;
            cpa16(as_base + (s * G_TS + row * 36 + ch * 4) * 4, ga, pa);
            bool pb = (bn + row) < SROWS;
            const __nv_bfloat16* gb =
                Bm + (size_t)(pb ? bn + row : 0) * DOUT + k0 + ch * 8;
            cpa16(bs_base + (s * G_TS + row * 36 + ch * 4) * 4, gb, pb);
        }
    };

    const int KT = DOUT / 64;   // 18
    load_stage(0, 0);
    CP_COMMIT();
    int buf = 0;
    for (int kt = 0; kt < KT; kt++) {
        if (kt + 1 < KT) {
            load_stage(buf ^ 1, (kt + 1) * 64);
            CP_COMMIT();
            CP_WAIT(1);
        } else {
            CP_WAIT(0);
        }
        __syncthreads();
        const unsigned* Aq = As + buf * G_TS;
        const unsigned* Bq = Bs + buf * G_TS;
#pragma unroll
        for (int ks = 0; ks < 4; ks++) {
            int kw = ks * 8;
            unsigned af[4][4];
#pragma unroll
            for (int mi = 0; mi < 4; mi++) {
                int m = wm + mi * 16 + lg;
                af[mi][0] = Aq[m * 36 + kw + lr];
                af[mi][1] = Aq[(m + 8) * 36 + kw + lr];
                af[mi][2] = Aq[m * 36 + kw + lr + 4];
                af[mi][3] = Aq[(m + 8) * 36 + kw + lr + 4];
            }
#pragma unroll
            for (int ni = 0; ni < 8; ni++) {
                int n = wn + ni * 8 + lg;
                unsigned b0 = Bq[n * 36 + kw + lr];
                unsigned b1 = Bq[n * 36 + kw + lr + 4];
#pragma unroll
                for (int mi = 0; mi < 4; mi++)
                    mma16(acc[mi][ni], af[mi], b0, b1);
            }
        }
        __syncthreads();
        buf ^= 1;
    }
#pragma unroll
    for (int mi = 0; mi < 4; mi++) {
        int r0 = bm + wm + mi * 16 + lg;
        int r1 = r0 + 8;
#pragma unroll
        for (int ni = 0; ni < 8; ni++) {
            int cb = bn + wn + ni * 8 + lr * 2;
            if (cb < SROWS) {
                if (r0 < QROWS) {
                    float* p = &d_S[(size_t)r0 * SROWS + cb];
                    p[0] = acc[mi][ni][0] * SCALE_QK;
                    p[1] = acc[mi][ni][1] * SCALE_QK;
                }
                if (r1 < QROWS) {
                    float* p = &d_S[(size_t)r1 * SROWS + cb];
                    p[0] = acc[mi][ni][2] * SCALE_QK;
                    p[1] = acc[mi][ni][3] * SCALE_QK;
                }
            }
        }
    }
}

// ---------------- stage E: segmented softmax, one warp per (row, class) --------
__global__ void softmax_kernel() {
    int tid = threadIdx.x, wid = tid >> 5, lane = tid & 31;
    int row = blockIdx.x * 8 + wid;
    int m = row / WAYS, c = row - m * WAYS;
    const float* p = d_S + (size_t)m * SROWS + c * 280;
    __nv_bfloat16* po = d_At + ((size_t)m * WAYS + c) * 320;

    float v[9];
    float mx = -3.4e38f;
#pragma unroll
    for (int e = 0; e < 9; e++) {
        int idx = lane + e * 32;
        if (idx < 280) { v[e] = p[idx]; mx = fmaxf(mx, v[e]); }
        else v[e] = -3.4e38f;
    }
#pragma unroll
    for (int o = 16; o; o >>= 1) mx = fmaxf(mx, __shfl_xor_sync(0xffffffffu, mx, o));

    float sum = 0.f;
#pragma unroll
    for (int e = 0; e < 9; e++) {
        int idx = lane + e * 32;
        if (idx < 280) { v[e] = expf(v[e] - mx); sum += v[e]; }
    }
#pragma unroll
    for (int o = 16; o; o >>= 1) sum += __shfl_xor_sync(0xffffffffu, sum, o);
    float inv = 1.0f / sum;
#pragma unroll
    for (int e = 0; e < 9; e++) {
        int idx = lane + e * 32;
        if (idx < 280) {
            int shd = idx / NTUP, t = idx - shd * NTUP;
            po[shd * 64 + t] = __float2bfloat16_rn(v[e] * inv);
        }
    }
    if (lane < 8) {
#pragma unroll
        for (int shd = 0; shd < SHOTS; shd++)
            po[shd * 64 + 56 + lane] = __float2bfloat16_rn(0.f);
    }
}

// ---------------- stage F: fused proto + partial logits, d-split x3 ------------
// grid (WAYS, NQ/2, 3), block 256 (8 warps: 4m x 2n over M=128, N=64 half-chunks)
#define F_PW 164                       // u32 words per row (pitch 328 bf16), %32==4
#define F_SMEM (128 * F_PW * 4 + 2 * 64 * F_PW * 4)   // attn + 2 cv half-buffers

__global__ void proto_logits_tc() {
    extern __shared__ unsigned sh[];
    unsigned* attn_w = sh;                 // [128][164] : rows 0..63 q0, 64..127 q0+1
    unsigned* cv_w = sh + 128 * F_PW;      // [2][64][164]
    unsigned attn_base = (unsigned)__cvta_generic_to_shared(attn_w);
    unsigned cv_base = (unsigned)__cvta_generic_to_shared(cv_w);

    int c = blockIdx.x, q0 = blockIdx.y * 2, zi = blockIdx.z;
    int d_base = zi * 384;                 // this CTA's 384-wide d slice
    int tid = threadIdx.x, lane = tid & 31, wid = tid >> 5;
    int wm = (wid & 3) * 16, wn = (wid >> 2) * 32;
    int lg = lane >> 2, lr = lane & 3;

    // attn for both queries: 128 rows x 40 16B-chunks (group 0)
    for (int f = tid; f < 128 * 40; f += 256) {
        int rr = f / 40, ch = f - rr * 40;
        int qq = rr >> 6, a = rr & 63;
        if (a < NTUP) {
            const __nv_bfloat16* src =
                d_At + ((size_t)((q0 + qq) * NTUP + a) * WAYS + c) * 320 + ch * 8;
            cpa16(attn_base + (rr * F_PW + ch * 4) * 4, src, true);
        } else {
            *(uint4*)((char*)attn_w + (rr * F_PW + ch * 4) * 4) =
                make_uint4(0, 0, 0, 0);
        }
    }
    CP_COMMIT();

    // cv half-chunk loader: 64 d-rows x 320 k
    auto load_cv = [&](int h, int b) {
        int d0 = d_base + h * 64;
        for (int f = tid; f < 64 * 40; f += 256) {
            int n = f / 40, ch = f - n * 40;
            const __nv_bfloat16* src =
                d_Vtt + ((size_t)c * DOUT + d0 + n) * 320 + ch * 8;
            cpa16(cv_base + ((b * 64 + n) * F_PW + ch * 4) * 4, src, true);
        }
    };

    load_cv(0, 0);
    CP_COMMIT();

    float total[2] = {0.f, 0.f};
    for (int h = 0; h < 6; h++) {
        int b = h & 1;
        if (h + 1 < 6) {
            load_cv(h + 1, b ^ 1);
            CP_COMMIT();
            CP_WAIT(1);
        } else {
            CP_WAIT(0);
        }
        __syncthreads();

        float acc[2][4][4];
#pragma unroll
        for (int mi = 0; mi < 2; mi++)
#pragma unroll
            for (int ni = 0; ni < 4; ni++)
#pragma unroll
                for (int e = 0; e < 4; e++) acc[mi][ni][e] = 0.f;

#pragma unroll
        for (int ks = 0; ks < 20; ks++) {
            int kw = ks * 8;
            unsigned af[2][4];
#pragma unroll
            for (int mi = 0; mi < 2; mi++) {
                int m = mi * 64 + wm + lg;
                af[mi][0] = attn_w[m * F_PW + kw + lr];
                af[mi][1] = attn_w[(m + 8) * F_PW + kw + lr];
                af[mi][2] = attn_w[m * F_PW + kw + lr + 4];
                af[mi][3] = attn_w[(m + 8) * F_PW + kw + lr + 4];
            }
#pragma unroll
            for (int ni = 0; ni < 4; ni++) {
                int nn = wn + ni * 8 + lg;
                unsigned b0 = cv_w[(b * 64 + nn) * F_PW + kw + lr];
                unsigned b1 = cv_w[(b * 64 + nn) * F_PW + kw + lr + 4];
                mma16(acc[0][ni], af[0], b0, b1);
                mma16(acc[1][ni], af[1], b0, b1);
            }
        }
        // ||qv - proto||^2 for this 64-d half-chunk, per query
        int d0 = d_base + h * 64;
        int r0 = wm + lg, r1 = r0 + 8;
#pragma unroll
        for (int mi = 0; mi < 2; mi++) {
            const float* qv0 =
                &d_V[(size_t)((NS + q0 + mi) * NTUP + r0) * DOUT];
            const float* qv1 = qv0 + (size_t)8 * DOUT;
#pragma unroll
            for (int ni = 0; ni < 4; ni++) {
                int col = d0 + wn + ni * 8 + lr * 2;
                if (r0 < NTUP) {
                    float e0 = qv0[col]     - acc[mi][ni][0];
                    float e1 = qv0[col + 1] - acc[mi][ni][1];
                    total[mi] += e0 * e0 + e1 * e1;
                }
                if (r1 < NTUP) {
                    float e2 = qv1[col]     - acc[mi][ni][2];
                    float e3 = qv1[col + 1] - acc[mi][ni][3];
                    total[mi] += e2 * e2 + e3 * e3;
                }
            }
        }
        __syncthreads();   // all warps done reading cv buf b before it is reloaded
    }
#pragma unroll
    for (int o = 16; o; o >>= 1) {
        total[0] += __shfl_xor_sync(0xffffffffu, total[0], o);
        total[1] += __shfl_xor_sync(0xffffffffu, total[1], o);
    }
    float* red = (float*)attn_w;
    if (lane == 0) { red[wid * 2] = total[0]; red[wid * 2 + 1] = total[1]; }
    __syncthreads();
    if (tid < 2) {
        float s = 0.f;
#pragma unroll
        for (int i = 0; i < 8; i++) s += red[i * 2 + tid];
        d_part[((q0 + tid) * WAYS + c) * 3 + zi] = s;
    }
}

// ---------------- stage G: reduce partials -> logits ---------------------------
__global__ void reduce_kernel(float* __restrict__ out) {
    int i = blockIdx.x * blockDim.x + threadIdx.x;
    if (i < NQ * WAYS)
        out[i] = -(d_part[i * 3] + d_part[i * 3 + 1] + d_part[i * 3 + 2])
                 * (1.0f / (float)NTUP);
}

// ---------------- launch ----------------
extern "C" void kernel_launch(void* const* d_in, const int* in_sizes, int n_in,
                              void* d_out, int out_size) {
    const float* sup = (const float*)d_in[0];
    const float* qry = (const float*)d_in[1];
    const float* Wk  = (const float*)d_in[3];
    const float* bk  = (const float*)d_in[4];
    const float* Wv  = (const float*)d_in[5];
    const float* bv  = (const float*)d_in[6];
    const float* lnw = (const float*)d_in[7];
    const float* lnb = (const float*)d_in[8];
    float* out = (float*)d_out;

    cudaFuncSetAttribute(gemm_main_tc,
                         cudaFuncAttributeMaxDynamicSharedMemorySize, G_SMEM);
    cudaFuncSetAttribute(gemm_scores_tc,
                         cudaFuncAttributeMaxDynamicSharedMemorySize, G_SMEM);
    cudaFuncSetAttribute(proto_logits_tc,
                         cudaFuncAttributeMaxDynamicSharedMemorySize, F_SMEM);

    dim3 gw(DIN / 32, DOUT / 32, 6);
    conv_wt_kernel<<<gw, dim3(32, 8)>>>(Wk, Wv);

    pe_add_kernel<<<XROWS, 256>>>(sup, qry);

    dim3 g1(DOUT / 128, (MROWS + 127) / 128, 6);
    gemm_main_tc<<<g1, 128, G_SMEM>>>();

    tuple_ln_kernel<<<KROWS, 128>>>(bk, bv, lnw, lnb);

    dim3 gv((280 + 31) / 32, DOUT / 32, WAYS);
    vtrans_kernel<<<gv, dim3(32, 8)>>>();

    dim3 g2((SROWS + 127) / 128, (QROWS + 127) / 128);
    gemm_scores_tc<<<g2, 128, G_SMEM>>>();

    softmax_kernel<<<(QROWS * WAYS) / 8, 256>>>();

    dim3 g4(WAYS, NQ / 2, 3);
    proto_logits_tc<<<g4, 256, F_SMEM>>>();

    reduce_kernel<<<4, 256>>>(out);
}